// round 3
// baseline (speedup 1.0000x reference)
#include <cuda_runtime.h>

#define NN 8192
#define DD 128
#define BM 128
#define BN 128
#define BK 32
#define BKP 36          // padded K stride (keeps float4 STS 16B-aligned)
#define TILES 64        // 8192 / 128
#define NBLK (TILES*TILES)

__device__ float g_partial[NBLK];

__global__ __launch_bounds__(256, 2)
void sim_loss_kernel(const float* __restrict__ X,
                     const float* __restrict__ margin,
                     const int* __restrict__ tgt)
{
    __shared__ float As[BM][BKP];
    __shared__ float Bs[BN][BKP];

    const int tid = threadIdx.x;
    const int tx  = tid & 15;        // 0..15  -> cols tx + 16*j
    const int ty  = tid >> 4;        // 0..15  -> rows ty + 16*i

    const int rowBase = blockIdx.y * BM;
    const int colBase = blockIdx.x * BN;

    float acc[8][8];
#pragma unroll
    for (int i = 0; i < 8; i++)
#pragma unroll
        for (int j = 0; j < 8; j++) acc[i][j] = 0.0f;

#pragma unroll
    for (int kc = 0; kc < DD / BK; kc++) {
        const int k0 = kc * BK;
        // load A and B tiles: 128 rows x 32 floats each = 1024 float4 per tile
#pragma unroll
        for (int p = 0; p < 4; p++) {
            int id  = tid + p * 256;
            int row = id >> 3;          // 0..127
            int k4  = (id & 7) * 4;     // 0,4,...,28
            float4 va = *(const float4*)&X[(size_t)(rowBase + row) * DD + k0 + k4];
            *(float4*)&As[row][k4] = va;
            float4 vb = *(const float4*)&X[(size_t)(colBase + row) * DD + k0 + k4];
            *(float4*)&Bs[row][k4] = vb;
        }
        __syncthreads();

#pragma unroll
        for (int kk = 0; kk < BK; kk++) {
            float a[8], b[8];
#pragma unroll
            for (int i = 0; i < 8; i++) a[i] = As[ty + 16 * i][kk];
#pragma unroll
            for (int j = 0; j < 8; j++) b[j] = Bs[tx + 16 * j][kk];
#pragma unroll
            for (int i = 0; i < 8; i++)
#pragma unroll
                for (int j = 0; j < 8; j++)
                    acc[i][j] = fmaf(a[i], b[j], acc[i][j]);
        }
        __syncthreads();
    }

    // ---- fused epilogue: masks + local reduction ----
    int   tr[8], tc[8];
    float mg[8];
#pragma unroll
    for (int i = 0; i < 8; i++) {
        int r = rowBase + ty + 16 * i;
        tr[i] = tgt[r];
        mg[i] = margin[r];
    }
#pragma unroll
    for (int j = 0; j < 8; j++) tc[j] = tgt[colBase + tx + 16 * j];

    float local = 0.0f;
#pragma unroll
    for (int i = 0; i < 8; i++) {
#pragma unroll
        for (int j = 0; j < 8; j++) {
            float s = acc[i][j];
            if (tr[i] == tc[j]) {
                if (s < 1.0f) local += 1.0f - s;
            } else {
                if (s > mg[i]) local += s;
            }
        }
    }

    // warp reduce
#pragma unroll
    for (int off = 16; off > 0; off >>= 1)
        local += __shfl_xor_sync(0xFFFFFFFFu, local, off);

    __shared__ float red[8];
    int wid = tid >> 5;
    if ((tid & 31) == 0) red[wid] = local;
    __syncthreads();
    if (tid == 0) {
        float s = 0.0f;
#pragma unroll
        for (int w = 0; w < 8; w++) s += red[w];
        g_partial[blockIdx.y * TILES + blockIdx.x] = s;
    }
}

__global__ void reduce_kernel(float* __restrict__ out)
{
    const int tid = threadIdx.x;   // 1024 threads
    float local = 0.0f;
#pragma unroll
    for (int p = 0; p < NBLK / 1024; p++)
        local += g_partial[tid + p * 1024];

#pragma unroll
    for (int off = 16; off > 0; off >>= 1)
        local += __shfl_xor_sync(0xFFFFFFFFu, local, off);

    __shared__ float red[32];
    int wid = tid >> 5;
    if ((tid & 31) == 0) red[wid] = local;
    __syncthreads();
    if (tid == 0) {
        float s = 0.0f;
#pragma unroll
        for (int w = 0; w < 32; w++) s += red[w];
        out[0] = s / (float)NN;
    }
}

extern "C" void kernel_launch(void* const* d_in, const int* in_sizes, int n_in,
                              void* d_out, int out_size)
{
    const float* X      = (const float*)d_in[0];
    const float* margin = (const float*)d_in[1];
    const int*   tgt    = (const int*)d_in[2];
    float*       out    = (float*)d_out;

    dim3 grid(TILES, TILES);
    sim_loss_kernel<<<grid, 256>>>(X, margin, tgt);
    reduce_kernel<<<1, 1024>>>(out);
}

// round 5
// speedup vs baseline: 5.7353x; 5.7353x over previous
#include <cuda_runtime.h>
#include <cuda_fp16.h>
#include <cstdint>

#define NN 8192
#define DD 128
#define BM 128
#define BN 128
#define BK 64
#define STR 72            // smem K-stride in halves (144 B = 36 words; 36%32=4 -> conflict-free ldmatrix)
#define TILES 64
#define NBLK (TILES*TILES)

__device__ __half X16[NN * DD];   // fp16 copy of inputs (2 MB)
__device__ float  g_partial[NBLK];
__device__ int    g_count;        // zero-init; last block resets -> graph-replay safe

__device__ __forceinline__ uint32_t smem_u32(const void* p) {
    uint32_t a;
    asm("{ .reg .u64 t; cvta.to.shared.u64 t, %1; cvt.u32.u64 %0, t; }" : "=r"(a) : "l"(p));
    return a;
}

__device__ __forceinline__ void ldsm_x4(uint32_t& r0, uint32_t& r1, uint32_t& r2, uint32_t& r3,
                                        uint32_t addr) {
    asm volatile("ldmatrix.sync.aligned.m8n8.x4.shared.b16 {%0,%1,%2,%3}, [%4];"
                 : "=r"(r0), "=r"(r1), "=r"(r2), "=r"(r3) : "r"(addr));
}

__device__ __forceinline__ void mma16816(float* c, uint32_t a0, uint32_t a1, uint32_t a2,
                                         uint32_t a3, uint32_t b0, uint32_t b1) {
    asm volatile("mma.sync.aligned.m16n8k16.row.col.f32.f16.f16.f32 "
                 "{%0,%1,%2,%3}, {%4,%5,%6,%7}, {%8,%9}, {%0,%1,%2,%3};"
                 : "+f"(c[0]), "+f"(c[1]), "+f"(c[2]), "+f"(c[3])
                 : "r"(a0), "r"(a1), "r"(a2), "r"(a3), "r"(b0), "r"(b1));
}

// ---------------- kernel 1: fp32 -> fp16 convert ----------------
__global__ void convert_kernel(const float* __restrict__ X) {
    int idx = (blockIdx.x * blockDim.x + threadIdx.x) * 4;
    float4 v = *(const float4*)&X[idx];
    __half2* o = (__half2*)&X16[idx];
    o[0] = __floats2half2_rn(v.x, v.y);
    o[1] = __floats2half2_rn(v.z, v.w);
}

// ---------------- kernel 2: fused HMMA GEMM + mask + reduce ----------------
__global__ __launch_bounds__(256, 2)
void sim_loss_mma(const float* __restrict__ margin,
                  const int* __restrict__ tgt,
                  float* __restrict__ out) {
    __shared__ __half As[BM * STR];
    __shared__ __half Bs[BN * STR];
    __shared__ int   cs[BN];      // col targets
    __shared__ int   rt[BM];      // row targets
    __shared__ float rm[BM];      // row margins
    __shared__ float red[8];
    __shared__ int   flag;

    const int tid  = threadIdx.x;
    const int lane = tid & 31;
    const int wid  = tid >> 5;
    const int wm   = wid & 1;     // 2 m-blocks of 64
    const int wn   = wid >> 1;    // 4 n-blocks of 32
    const int rowBase = blockIdx.y * BM;
    const int colBase = blockIdx.x * BN;

    const uint32_t sA = smem_u32(As);
    const uint32_t sB = smem_u32(Bs);

    float acc[4][4][4];
#pragma unroll
    for (int mi = 0; mi < 4; mi++)
#pragma unroll
        for (int ni = 0; ni < 4; ni++)
#pragma unroll
            for (int q = 0; q < 4; q++) acc[mi][ni][q] = 0.0f;

    if (tid < 128) {
        cs[tid] = tgt[colBase + tid];
        rt[tid] = tgt[rowBase + tid];
        rm[tid] = margin[rowBase + tid];
    }

#pragma unroll
    for (int kc = 0; kc < DD / BK; kc++) {
        const int k0 = kc * BK;
        // ---- load A,B: 128 rows x 64 halves (128 B) each -> 1024 uint4 per tile ----
#pragma unroll
        for (int p = 0; p < 4; p++) {
            int id  = tid + p * 256;
            int row = id >> 3;          // 0..127
            int ch  = id & 7;           // 16B chunk
            uint4 va = *(const uint4*)&X16[(size_t)(rowBase + row) * DD + k0 + ch * 8];
            *(uint4*)&As[row * STR + ch * 8] = va;
            uint4 vb = *(const uint4*)&X16[(size_t)(colBase + row) * DD + k0 + ch * 8];
            *(uint4*)&Bs[row * STR + ch * 8] = vb;
        }
        __syncthreads();

        // ---- 4 K-steps of 16 ----
#pragma unroll
        for (int ks = 0; ks < BK / 16; ks++) {
            const int lrow = lane & 15;
            const int lchk = lane >> 4;       // 0/1 -> second 16B chunk
            uint32_t a[4][4];
#pragma unroll
            for (int mi = 0; mi < 4; mi++) {
                uint32_t addr = sA + ((wm * 64 + mi * 16 + lrow) * STR + ks * 16 + lchk * 8) * 2;
                ldsm_x4(a[mi][0], a[mi][1], a[mi][2], a[mi][3], addr);
            }
            uint32_t b[2][4];
#pragma unroll
            for (int nb = 0; nb < 2; nb++) {
                uint32_t addr = sB + ((wn * 32 + nb * 16 + lrow) * STR + ks * 16 + lchk * 8) * 2;
                ldsm_x4(b[nb][0], b[nb][1], b[nb][2], b[nb][3], addr);
            }
            // b mapping: r0,r1 = n-tiles (0,1) k-low; r2,r3 = n-tiles (0,1) k-high
#pragma unroll
            for (int mi = 0; mi < 4; mi++)
#pragma unroll
                for (int ni = 0; ni < 4; ni++)
                    mma16816(acc[mi][ni], a[mi][0], a[mi][1], a[mi][2], a[mi][3],
                             b[ni >> 1][ni & 1], b[ni >> 1][2 + (ni & 1)]);
        }
        __syncthreads();
    }

    // ---- epilogue: masks on fragment layout, local sum ----
    // c0:(r,c) c1:(r,c+1) c2:(r+8,c) c3:(r+8,c+1); r = lane/4, c = 2*(lane&3)
    const int r0l = (lane >> 2);
    const int c0l = (lane & 3) * 2;
    float local = 0.0f;
#pragma unroll
    for (int mi = 0; mi < 4; mi++) {
        const int rA = wm * 64 + mi * 16 + r0l;
        const int rB = rA + 8;
        const int   trA = rt[rA], trB = rt[rB];
        const float mgA = rm[rA], mgB = rm[rB];
#pragma unroll
        for (int ni = 0; ni < 4; ni++) {
            const int c0 = wn * 32 + ni * 8 + c0l;
            const int tc0 = cs[c0], tc1 = cs[c0 + 1];
            float s;
            s = acc[mi][ni][0];
            if (trA == tc0) { if (s < 1.0f) local += 1.0f - s; } else if (s > mgA) local += s;
            s = acc[mi][ni][1];
            if (trA == tc1) { if (s < 1.0f) local += 1.0f - s; } else if (s > mgA) local += s;
            s = acc[mi][ni][2];
            if (trB == tc0) { if (s < 1.0f) local += 1.0f - s; } else if (s > mgB) local += s;
            s = acc[mi][ni][3];
            if (trB == tc1) { if (s < 1.0f) local += 1.0f - s; } else if (s > mgB) local += s;
        }
    }

    // ---- block reduce ----
#pragma unroll
    for (int off = 16; off > 0; off >>= 1)
        local += __shfl_xor_sync(0xFFFFFFFFu, local, off);
    if (lane == 0) red[wid] = local;
    __syncthreads();

    const int bid = blockIdx.y * TILES + blockIdx.x;
    if (tid == 0) {
        float s = 0.0f;
#pragma unroll
        for (int w = 0; w < 8; w++) s += red[w];
        g_partial[bid] = s;
    }

    // ---- deterministic last-block final reduce ----
    __threadfence();
    __syncthreads();
    if (tid == 0) flag = (atomicAdd(&g_count, 1) == NBLK - 1) ? 1 : 0;
    __syncthreads();
    if (flag) {
        float v = 0.0f;
#pragma unroll
        for (int p = 0; p < NBLK / 256; p++)
            v += g_partial[tid + p * 256];
#pragma unroll
        for (int off = 16; off > 0; off >>= 1)
            v += __shfl_xor_sync(0xFFFFFFFFu, v, off);
        if (lane == 0) red[wid] = v;
        __syncthreads();
        if (tid == 0) {
            float s = 0.0f;
#pragma unroll
            for (int w = 0; w < 8; w++) s += red[w];
            out[0] = s / (float)NN;
            g_count = 0;   // restore for next graph replay
        }
    }
}

// ---------------- launcher ----------------
extern "C" void kernel_launch(void* const* d_in, const int* in_sizes, int n_in,
                              void* d_out, int out_size) {
    const float* X      = (const float*)d_in[0];
    const float* margin = (const float*)d_in[1];
    const int*   tgt    = (const int*)d_in[2];
    float*       out    = (float*)d_out;

    convert_kernel<<<NN * DD / 4 / 256, 256>>>(X);
    dim3 grid(TILES, TILES);
    sim_loss_mma<<<grid, 256>>>(margin, tgt, out);
}

// round 6
// speedup vs baseline: 8.9102x; 1.5536x over previous
#include <cuda_runtime.h>
#include <cuda_fp16.h>
#include <cstdint>

#define NN 8192
#define DD 128
#define BM 128
#define BN 128
#define BK 64
#define STR 72            // smem K-stride in halves; conflict-free ldmatrix
#define TILES 64
#define NBLK (TILES*TILES)
#define NACT (TILES*(TILES+1)/2)   // active (upper-triangle) blocks = 2080

__device__ __half X16[NN * DD];   // fp16 copy of inputs (2 MB)
__device__ float  g_partial[NBLK];
__device__ int    g_count;        // zero-init; last active block resets

__device__ __forceinline__ uint32_t smem_u32(const void* p) {
    uint32_t a;
    asm("{ .reg .u64 t; cvta.to.shared.u64 t, %1; cvt.u32.u64 %0, t; }" : "=r"(a) : "l"(p));
    return a;
}

__device__ __forceinline__ void ldsm_x4(uint32_t& r0, uint32_t& r1, uint32_t& r2, uint32_t& r3,
                                        uint32_t addr) {
    asm volatile("ldmatrix.sync.aligned.m8n8.x4.shared.b16 {%0,%1,%2,%3}, [%4];"
                 : "=r"(r0), "=r"(r1), "=r"(r2), "=r"(r3) : "r"(addr));
}

__device__ __forceinline__ void mma16816(float* c, uint32_t a0, uint32_t a1, uint32_t a2,
                                         uint32_t a3, uint32_t b0, uint32_t b1) {
    asm volatile("mma.sync.aligned.m16n8k16.row.col.f32.f16.f16.f32 "
                 "{%0,%1,%2,%3}, {%4,%5,%6,%7}, {%8,%9}, {%0,%1,%2,%3};"
                 : "+f"(c[0]), "+f"(c[1]), "+f"(c[2]), "+f"(c[3])
                 : "r"(a0), "r"(a1), "r"(a2), "r"(a3), "r"(b0), "r"(b1));
}

// ---------------- kernel 1: fp32 -> fp16 convert ----------------
__global__ void convert_kernel(const float* __restrict__ X) {
    int idx = (blockIdx.x * blockDim.x + threadIdx.x) * 4;
    float4 v = *(const float4*)&X[idx];
    __half2* o = (__half2*)&X16[idx];
    o[0] = __floats2half2_rn(v.x, v.y);
    o[1] = __floats2half2_rn(v.z, v.w);
}

// ---------------- kernel 2: fused HMMA GEMM + mask + reduce (upper triangle) ----------------
__global__ __launch_bounds__(256, 2)
void sim_loss_mma(const float* __restrict__ margin,
                  const int* __restrict__ tgt,
                  float* __restrict__ out) {
    // upper triangle only: row-tile by <= col-tile bx
    if (blockIdx.y > blockIdx.x) return;
    const bool diag = (blockIdx.y == blockIdx.x);

    __shared__ __half As[BM * STR];
    __shared__ __half Bs[BN * STR];
    __shared__ int   cs[BN];      // col targets
    __shared__ float cm[BN];      // col margins
    __shared__ int   rt[BM];      // row targets
    __shared__ float rm[BM];      // row margins
    __shared__ float red[8];
    __shared__ int   flag;

    const int tid  = threadIdx.x;
    const int lane = tid & 31;
    const int wid  = tid >> 5;
    const int wm   = wid & 1;     // 2 m-blocks of 64
    const int wn   = wid >> 1;    // 4 n-blocks of 32
    const int rowBase = blockIdx.y * BM;
    const int colBase = blockIdx.x * BN;

    const uint32_t sA = smem_u32(As);
    const uint32_t sB = smem_u32(Bs);

    float acc[4][4][4];
#pragma unroll
    for (int mi = 0; mi < 4; mi++)
#pragma unroll
        for (int ni = 0; ni < 4; ni++)
#pragma unroll
            for (int q = 0; q < 4; q++) acc[mi][ni][q] = 0.0f;

    if (tid < 128) {
        cs[tid] = tgt[colBase + tid];
        cm[tid] = margin[colBase + tid];
        rt[tid] = tgt[rowBase + tid];
        rm[tid] = margin[rowBase + tid];
    }

#pragma unroll
    for (int kc = 0; kc < DD / BK; kc++) {
        const int k0 = kc * BK;
#pragma unroll
        for (int p = 0; p < 4; p++) {
            int id  = tid + p * 256;
            int row = id >> 3;          // 0..127
            int ch  = id & 7;           // 16B chunk
            uint4 va = *(const uint4*)&X16[(size_t)(rowBase + row) * DD + k0 + ch * 8];
            *(uint4*)&As[row * STR + ch * 8] = va;
            uint4 vb = *(const uint4*)&X16[(size_t)(colBase + row) * DD + k0 + ch * 8];
            *(uint4*)&Bs[row * STR + ch * 8] = vb;
        }
        __syncthreads();

#pragma unroll
        for (int ks = 0; ks < BK / 16; ks++) {
            const int lrow = lane & 15;
            const int lchk = lane >> 4;
            uint32_t a[4][4];
#pragma unroll
            for (int mi = 0; mi < 4; mi++) {
                uint32_t addr = sA + ((wm * 64 + mi * 16 + lrow) * STR + ks * 16 + lchk * 8) * 2;
                ldsm_x4(a[mi][0], a[mi][1], a[mi][2], a[mi][3], addr);
            }
            uint32_t b[2][4];
#pragma unroll
            for (int nb = 0; nb < 2; nb++) {
                uint32_t addr = sB + ((wn * 32 + nb * 16 + lrow) * STR + ks * 16 + lchk * 8) * 2;
                ldsm_x4(b[nb][0], b[nb][1], b[nb][2], b[nb][3], addr);
            }
#pragma unroll
            for (int mi = 0; mi < 4; mi++)
#pragma unroll
                for (int ni = 0; ni < 4; ni++)
                    mma16816(acc[mi][ni], a[mi][0], a[mi][1], a[mi][2], a[mi][3],
                             b[ni >> 1][ni & 1], b[ni >> 1][2 + (ni & 1)]);
        }
        __syncthreads();
    }

    // ---- epilogue ----
    // fragment: c0:(r,c) c1:(r,c+1) c2:(r+8,c) c3:(r+8,c+1); r=lane/4, c=2*(lane&3)
    const int r0l = (lane >> 2);
    const int c0l = (lane & 3) * 2;
    float local = 0.0f;

#pragma unroll
    for (int mi = 0; mi < 4; mi++) {
        const int rA = wm * 64 + mi * 16 + r0l;
        const int rB = rA + 8;
        const int   trA = rt[rA], trB = rt[rB];
        const float mgA = rm[rA], mgB = rm[rB];
#pragma unroll
        for (int ni = 0; ni < 4; ni++) {
            const int c0 = wn * 32 + ni * 8 + c0l;
            const int   tc0 = cs[c0],     tc1 = cs[c0 + 1];
            const float mc0 = cm[c0],     mc1 = cm[c0 + 1];
            float s;
            if (diag) {
                s = acc[mi][ni][0];
                if (trA == tc0) { if (s < 1.0f) local += 1.0f - s; } else if (s > mgA) local += s;
                s = acc[mi][ni][1];
                if (trA == tc1) { if (s < 1.0f) local += 1.0f - s; } else if (s > mgA) local += s;
                s = acc[mi][ni][2];
                if (trB == tc0) { if (s < 1.0f) local += 1.0f - s; } else if (s > mgB) local += s;
                s = acc[mi][ni][3];
                if (trB == tc1) { if (s < 1.0f) local += 1.0f - s; } else if (s > mgB) local += s;
            } else {
                // off-diagonal: emit (i,j) and (j,i) together
                s = acc[mi][ni][0];
                if (trA == tc0) { if (s < 1.0f) local += 2.0f * (1.0f - s); }
                else { if (s > mgA) local += s; if (s > mc0) local += s; }
                s = acc[mi][ni][1];
                if (trA == tc1) { if (s < 1.0f) local += 2.0f * (1.0f - s); }
                else { if (s > mgA) local += s; if (s > mc1) local += s; }
                s = acc[mi][ni][2];
                if (trB == tc0) { if (s < 1.0f) local += 2.0f * (1.0f - s); }
                else { if (s > mgB) local += s; if (s > mc0) local += s; }
                s = acc[mi][ni][3];
                if (trB == tc1) { if (s < 1.0f) local += 2.0f * (1.0f - s); }
                else { if (s > mgB) local += s; if (s > mc1) local += s; }
            }
        }
    }

    // ---- block reduce ----
#pragma unroll
    for (int off = 16; off > 0; off >>= 1)
        local += __shfl_xor_sync(0xFFFFFFFFu, local, off);
    if (lane == 0) red[wid] = local;
    __syncthreads();

    const int bid = blockIdx.y * TILES + blockIdx.x;
    if (tid == 0) {
        float s = 0.0f;
#pragma unroll
        for (int w = 0; w < 8; w++) s += red[w];
        g_partial[bid] = s;
    }

    // ---- deterministic last-active-block final reduce ----
    // inactive (lower-triangle) g_partial entries are never written: they keep
    // their zero static-initialization, so summing all NBLK slots is exact.
    __threadfence();
    __syncthreads();
    if (tid == 0) flag = (atomicAdd(&g_count, 1) == NACT - 1) ? 1 : 0;
    __syncthreads();
    if (flag) {
        float v = 0.0f;
#pragma unroll
        for (int p = 0; p < NBLK / 256; p++)
            v += g_partial[tid + p * 256];
#pragma unroll
        for (int off = 16; off > 0; off >>= 1)
            v += __shfl_xor_sync(0xFFFFFFFFu, v, off);
        if (lane == 0) red[wid] = v;
        __syncthreads();
        if (tid == 0) {
            float s = 0.0f;
#pragma unroll
            for (int w = 0; w < 8; w++) s += red[w];
            out[0] = s / (float)NN;
            g_count = 0;   // restore for next graph replay
        }
    }
}

// ---------------- launcher ----------------
extern "C" void kernel_launch(void* const* d_in, const int* in_sizes, int n_in,
                              void* d_out, int out_size) {
    const float* X      = (const float*)d_in[0];
    const float* margin = (const float*)d_in[1];
    const int*   tgt    = (const int*)d_in[2];
    float*       out    = (float*)d_out;

    convert_kernel<<<NN * DD / 4 / 256, 256>>>(X);
    dim3 grid(TILES, TILES);
    sim_loss_mma<<<grid, 256>>>(margin, tgt, out);
}